// round 15
// baseline (speedup 1.0000x reference)
#include <cuda_runtime.h>
#include <cuda_fp16.h>
#include <stdint.h>

#define N_NODES 100000
#define F_IN    512
#define HID     64
#define NCLS    64
#define BM      128
#define KCH     32
#define NCHUNK  (F_IN / KCH)   // 16
#define MAX_E   3200000
#define SCAN_NB ((N_NODES + 1023) / 1024)   // 98

// MLP pipeline geometry
#define XW      36                    // X stage row stride in floats (144B, 16B-aligned)
#define XSTAGE  (128 * XW)            // 4608 words per X stage
#define WW      72                    // W stage row stride in uint32 (half2)
#define WSTAGE  (16 * WW)             // 1152 words per W stage
#define NSTAGE  4
#define SMEM_WORDS ((XSTAGE + WSTAGE) * NSTAGE)   // 23040 words = 92160 B

// fp16 logits scratch [N_NODES, 64] = 12.8 MB.
__device__ __align__(256) __half g_logits_h[(size_t)N_NODES * NCLS];
// W1 pre-converted to fp16 k-pair layout: g_W1p[kp*64 + n] = {W1[2kp][n], W1[2kp+1][n]}
__device__ __align__(16) uint32_t g_W1p[256 * 64];
// CSR machinery
__device__ int  g_cnt[N_NODES];
__device__ int  g_off[N_NODES];
__device__ int  g_run[N_NODES];
__device__ int  g_bsum[SCAN_NB];
__device__ __align__(16) int2 g_epack[MAX_E];   // (col, val bits) sorted by row

__device__ __forceinline__ void mma_f16(float* c, const uint32_t* a, const uint32_t* b) {
    asm volatile("mma.sync.aligned.m16n8k16.row.col.f32.f16.f16.f32 "
        "{%0,%1,%2,%3}, {%4,%5,%6,%7}, {%8,%9}, {%0,%1,%2,%3};\n"
        : "+f"(c[0]), "+f"(c[1]), "+f"(c[2]), "+f"(c[3])
        : "r"(a[0]), "r"(a[1]), "r"(a[2]), "r"(a[3]), "r"(b[0]), "r"(b[1]));
}

__device__ __forceinline__ void cp16(uint32_t dst, const void* src, int bytes) {
    // bytes == 16: copy; bytes == 0: zero-fill (src not dereferenced)
    asm volatile("cp.async.cg.shared.global [%0], [%1], 16, %2;"
                 :: "r"(dst), "l"(src), "r"(bytes));
}
__device__ __forceinline__ void cp_commit() {
    asm volatile("cp.async.commit_group;");
}
__device__ __forceinline__ void cp_wait2() {
    asm volatile("cp.async.wait_group 2;");
}

// ---------------------------------------------------------------------------
// One-time W1 -> fp16 k-pair conversion (64 KB)
// ---------------------------------------------------------------------------
__global__ __launch_bounds__(256) void w1conv_k(const float* __restrict__ W1)
{
    int idx = blockIdx.x * 256 + threadIdx.x;   // 0..16383
    if (idx < 256 * 64) {
        int kp = idx >> 6;
        int n  = idx & 63;
        __half2 p = __floats2half2_rn(W1[(size_t)(2 * kp) * HID + n],
                                      W1[(size_t)(2 * kp + 1) * HID + n]);
        g_W1p[idx] = *(uint32_t*)&p;
    }
}

// ---------------------------------------------------------------------------
// Fused MLP, both GEMMs fp16 mma (fp32 accum), cp.async 4-stage pipeline.
//   h = relu(X @ W1 + b1); logits = h @ W2 + b2 -> fp16 store
// Block: 128 rows, 8 warps 4(M)x2(N); warp tile 32x32.
// X streams fp32 via cp.async (converted to fp16 at fragment load);
// W1 tiles stream pre-converted fp16 via cp.async.
// ---------------------------------------------------------------------------
__global__ __launch_bounds__(256) void mlp_mma(
    const float* __restrict__ X,
    const float* __restrict__ b1,
    const float* __restrict__ W2,
    const float* __restrict__ b2)
{
    extern __shared__ __align__(16) uint32_t smem[];
    float*    Xst = (float*)smem;                  // NSTAGE x [128][XW] fp32
    uint32_t* Wst = smem + XSTAGE * NSTAGE;        // NSTAGE x [16][WW] half2
    uint32_t (*H2)[36]  = (uint32_t(*)[36])smem;              // phase-2 overlay
    uint32_t (*W2p)[72] = (uint32_t(*)[72])(smem + XSTAGE);   // phase-2 overlay

    uint32_t sbase;
    asm("{ .reg .u64 t0; cvta.to.shared.u64 t0, %1; cvt.u32.u64 %0, t0; }"
        : "=r"(sbase) : "l"(smem));

    const int t    = threadIdx.x;
    const int lane = t & 31;
    const int wid  = t >> 5;
    const int wm   = wid & 3;
    const int wn   = wid >> 2;
    const int g    = lane >> 2;
    const int tq   = lane & 3;
    const int rb   = blockIdx.x * BM;

    // cp.async geometry (constant per thread)
    const int wr   = t >> 4;          // W row 0..15
    const int ww16 = (t & 15) * 4;    // W word offset (x4 uint32 = 16B)

    auto issue_chunk = [&](int cc) {
        const int kb = cc * KCH;
        const int st = cc & 3;
        // X: 128 rows x 32 floats = 1024 x 16B, 4 per thread
#pragma unroll
        for (int l = 0; l < 4; l++) {
            int idx  = t + l * 256;
            int row  = idx >> 3;
            int c16  = (idx & 7) * 4;
            int grow = rb + row;
            uint32_t dst = sbase + (uint32_t)(st * XSTAGE + row * XW + c16) * 4u;
            const float* src = X + (size_t)grow * F_IN + kb + c16;
            cp16(dst, src, grow < N_NODES ? 16 : 0);
        }
        // W: 16 rows x 64 uint32 = 256 x 16B, 1 per thread
        {
            uint32_t dst = sbase +
                (uint32_t)(XSTAGE * NSTAGE + st * WSTAGE + wr * WW + ww16) * 4u;
            const uint32_t* src = g_W1p + (size_t)(cc * 16 + wr) * 64 + ww16;
            cp16(dst, src, 16);
        }
        cp_commit();
    };

    float c1[2][4][4];
#pragma unroll
    for (int m = 0; m < 2; m++)
#pragma unroll
        for (int n = 0; n < 4; n++)
#pragma unroll
            for (int i = 0; i < 4; i++) c1[m][n][i] = 0.0f;

    issue_chunk(0);
    issue_chunk(1);
    issue_chunk(2);

#pragma unroll 1
    for (int cc = 0; cc < NCHUNK; cc++) {
        cp_wait2();          // group cc complete (<=2 younger groups pending)
        __syncthreads();     // all warps done reading stage (cc-1)&3

        if (cc + 3 < NCHUNK) issue_chunk(cc + 3);
        else                 cp_commit();   // empty group keeps the count

        const float*    Xs = Xst + (cc & 3) * XSTAGE;
        const uint32_t* Wp = Wst + (cc & 3) * WSTAGE;

#pragma unroll
        for (int ka = 0; ka < 2; ka++) {
            const int kp = ka * 8;
            uint32_t a[2][4];
#pragma unroll
            for (int m = 0; m < 2; m++) {
                int row = wm * 32 + m * 16;
                float2 f0 = *(const float2*)(Xs + (row + g    ) * XW + 2 * (kp + tq));
                float2 f1 = *(const float2*)(Xs + (row + g + 8) * XW + 2 * (kp + tq));
                float2 f2 = *(const float2*)(Xs + (row + g    ) * XW + 2 * (kp + tq + 4));
                float2 f3 = *(const float2*)(Xs + (row + g + 8) * XW + 2 * (kp + tq + 4));
                __half2 h0 = __floats2half2_rn(f0.x, f0.y);
                __half2 h1 = __floats2half2_rn(f1.x, f1.y);
                __half2 h2 = __floats2half2_rn(f2.x, f2.y);
                __half2 h3 = __floats2half2_rn(f3.x, f3.y);
                a[m][0] = *(uint32_t*)&h0;
                a[m][1] = *(uint32_t*)&h1;
                a[m][2] = *(uint32_t*)&h2;
                a[m][3] = *(uint32_t*)&h3;
            }
            uint32_t b[4][2];
#pragma unroll
            for (int n = 0; n < 4; n++) {
                int col = wn * 32 + n * 8 + g;
                b[n][0] = Wp[(kp + tq    ) * WW + col];
                b[n][1] = Wp[(kp + tq + 4) * WW + col];
            }
#pragma unroll
            for (int m = 0; m < 2; m++)
#pragma unroll
                for (int n = 0; n < 4; n++)
                    mma_f16(c1[m][n], a[m], b[n]);
        }
    }
    __syncthreads();   // all warps done with final chunk before overlaying

    // bias + relu -> fp16 pairs into H2 (overlays stage X0; safe per barrier)
#pragma unroll
    for (int n = 0; n < 4; n++) {
        float2 bb = *(const float2*)(b1 + wn * 32 + n * 8 + 2 * tq);
        int colp = wn * 16 + n * 4 + tq;
#pragma unroll
        for (int m = 0; m < 2; m++) {
            int row = wm * 32 + m * 16 + g;
            float h0 = fmaxf(c1[m][n][0] + bb.x, 0.f);
            float h1 = fmaxf(c1[m][n][1] + bb.y, 0.f);
            float h2 = fmaxf(c1[m][n][2] + bb.x, 0.f);
            float h3 = fmaxf(c1[m][n][3] + bb.y, 0.f);
            __half2 p0 = __floats2half2_rn(h0, h1);
            __half2 p1 = __floats2half2_rn(h2, h3);
            H2[row    ][colp] = *(uint32_t*)&p0;
            H2[row + 8][colp] = *(uint32_t*)&p1;
        }
    }
    // W2 -> fp16 k-pair layout (overlays stage X1 region)
#pragma unroll
    for (int l = 0; l < 8; l++) {
        int idx = t + l * 256;
        int kp  = idx >> 6;
        int n   = idx & 63;
        float w0 = W2[(size_t)(2 * kp    ) * NCLS + n];
        float w1 = W2[(size_t)(2 * kp + 1) * NCLS + n];
        __half2 p = __floats2half2_rn(w0, w1);
        W2p[kp][n] = *(uint32_t*)&p;
    }
    __syncthreads();

    float c2[2][4][4];
#pragma unroll
    for (int m = 0; m < 2; m++)
#pragma unroll
        for (int n = 0; n < 4; n++)
#pragma unroll
            for (int i = 0; i < 4; i++) c2[m][n][i] = 0.0f;

#pragma unroll
    for (int ka = 0; ka < 4; ka++) {
        const int kp = ka * 8;
        uint32_t a[2][4];
#pragma unroll
        for (int m = 0; m < 2; m++) {
            int row = wm * 32 + m * 16;
            a[m][0] = H2[row + g    ][kp + tq];
            a[m][1] = H2[row + g + 8][kp + tq];
            a[m][2] = H2[row + g    ][kp + tq + 4];
            a[m][3] = H2[row + g + 8][kp + tq + 4];
        }
        uint32_t b[4][2];
#pragma unroll
        for (int n = 0; n < 4; n++) {
            int col = wn * 32 + n * 8 + g;
            b[n][0] = W2p[kp + tq    ][col];
            b[n][1] = W2p[kp + tq + 4][col];
        }
#pragma unroll
        for (int m = 0; m < 2; m++)
#pragma unroll
            for (int n = 0; n < 4; n++)
                mma_f16(c2[m][n], a[m], b[n]);
    }

    // + b2, store logits as fp16
    __half2* lg2 = (__half2*)g_logits_h;
#pragma unroll
    for (int n = 0; n < 4; n++) {
        float2 bb = *(const float2*)(b2 + wn * 32 + n * 8 + 2 * tq);
        int colp = wn * 16 + n * 4 + tq;
#pragma unroll
        for (int m = 0; m < 2; m++) {
            int row = rb + wm * 32 + m * 16 + g;
            if (row < N_NODES)
                lg2[(size_t)row * 32 + colp] =
                    __floats2half2_rn(c2[m][n][0] + bb.x, c2[m][n][1] + bb.y);
            if (row + 8 < N_NODES)
                lg2[(size_t)(row + 8) * 32 + colp] =
                    __floats2half2_rn(c2[m][n][2] + bb.x, c2[m][n][3] + bb.y);
        }
    }
}

// ---------------------------------------------------------------------------
// CSR build: histogram -> scan -> scatter (4 edges/thread, vectorized)
// ---------------------------------------------------------------------------
__global__ __launch_bounds__(256) void hist_k(const int* __restrict__ rows, int E)
{
    int base = (blockIdx.x * 256 + threadIdx.x) * 4;
    if (base + 3 < E) {
        int4 r = *(const int4*)(rows + base);
        atomicAdd(&g_cnt[r.x], 1);
        atomicAdd(&g_cnt[r.y], 1);
        atomicAdd(&g_cnt[r.z], 1);
        atomicAdd(&g_cnt[r.w], 1);
    } else {
        for (int e = base; e < E; e++) atomicAdd(&g_cnt[rows[e]], 1);
    }
}

__global__ __launch_bounds__(256) void scan1_k(int n)
{
    __shared__ int wsum[8];
    const int t = threadIdx.x, b = blockIdx.x;
    const int base = b * 1024 + t * 4;
    int v0 = 0, v1 = 0, v2 = 0, v3 = 0;
    if (base + 0 < n) v0 = g_cnt[base + 0];
    if (base + 1 < n) v1 = g_cnt[base + 1];
    if (base + 2 < n) v2 = g_cnt[base + 2];
    if (base + 3 < n) v3 = g_cnt[base + 3];
    const int tsum = v0 + v1 + v2 + v3;
    const int lane = t & 31, w = t >> 5;
    int inc = tsum;
#pragma unroll
    for (int d = 1; d < 32; d <<= 1) {
        int y = __shfl_up_sync(0xffffffffu, inc, d);
        if (lane >= d) inc += y;
    }
    if (lane == 31) wsum[w] = inc;
    __syncthreads();
    if (t < 8) {
        int x = wsum[t];
#pragma unroll
        for (int d = 1; d < 8; d <<= 1) {
            int y = __shfl_up_sync(0xffu, x, d);
            if (t >= d) x += y;
        }
        wsum[t] = x;
    }
    __syncthreads();
    const int wprefix = (w == 0) ? 0 : wsum[w - 1];
    const int texcl = wprefix + inc - tsum;
    if (base + 0 < n) g_off[base + 0] = texcl;
    if (base + 1 < n) g_off[base + 1] = texcl + v0;
    if (base + 2 < n) g_off[base + 2] = texcl + v0 + v1;
    if (base + 3 < n) g_off[base + 3] = texcl + v0 + v1 + v2;
    if (t == 255) g_bsum[b] = wsum[7];
}

__global__ __launch_bounds__(128) void scan2_k(int nb)
{
    __shared__ int wsum[4];
    const int t = threadIdx.x;
    int x0 = (t < nb) ? g_bsum[t] : 0;
    const int lane = t & 31, w = t >> 5;
    int x = x0;
#pragma unroll
    for (int d = 1; d < 32; d <<= 1) {
        int y = __shfl_up_sync(0xffffffffu, x, d);
        if (lane >= d) x += y;
    }
    if (lane == 31) wsum[w] = x;
    __syncthreads();
    if (t < 4) {
        int y = wsum[t];
#pragma unroll
        for (int d = 1; d < 4; d <<= 1) {
            int z = __shfl_up_sync(0xfu, y, d);
            if (t >= d) y += z;
        }
        wsum[t] = y;
    }
    __syncthreads();
    const int wprefix = (w == 0) ? 0 : wsum[w - 1];
    if (t < nb) g_bsum[t] = wprefix + x - x0;   // exclusive
}

__global__ __launch_bounds__(256) void scan3_k(int n)
{
    int i = blockIdx.x * 256 + threadIdx.x;
    if (i < n) {
        int o = g_off[i] + g_bsum[i >> 10];
        g_off[i] = o;
        g_run[i] = o;
    }
}

__device__ __forceinline__ void epack_store(int p, int col, float val) {
    int2 e = make_int2(col, __float_as_int(val));
    __stcs(&g_epack[p], e);   // evict-first: don't displace logits in L2
}

__global__ __launch_bounds__(256) void build_k(
    const int* __restrict__ rows, const int* __restrict__ cols,
    const float* __restrict__ vals, int E)
{
    int base = (blockIdx.x * 256 + threadIdx.x) * 4;
    if (base + 3 < E) {
        int4   r = *(const int4*)(rows + base);
        int4   c = *(const int4*)(cols + base);
        float4 v = *(const float4*)(vals + base);
        epack_store(atomicAdd(&g_run[r.x], 1), c.x, v.x);
        epack_store(atomicAdd(&g_run[r.y], 1), c.y, v.y);
        epack_store(atomicAdd(&g_run[r.z], 1), c.z, v.z);
        epack_store(atomicAdd(&g_run[r.w], 1), c.w, v.w);
    } else {
        for (int e = base; e < E; e++)
            epack_store(atomicAdd(&g_run[rows[e]], 1), cols[e], vals[e]);
    }
}

// ---------------------------------------------------------------------------
// Reduce: one warp per node, four 8-lane groups, each unrolled x2 ->
// eight independent gather chains in flight per warp. Atomic-free.
// ---------------------------------------------------------------------------
__global__ __launch_bounds__(256) void reduce_k(float* __restrict__ out)
{
    const int wid  = threadIdx.x >> 5;
    const int lane = threadIdx.x & 31;
    const int n    = blockIdx.x * 8 + wid;
    if (n >= N_NODES) return;

    const int s   = g_off[n];
    const int m   = g_cnt[n];
    const int end = s + m;
    const int grp = lane >> 3;    // 0..3: edge-stream group
    const int j   = lane & 7;     // uint4 index within 64-col row

    const uint4* __restrict__ lg4 = (const uint4*)g_logits_h;  // row = 8 uint4

    float aA0 = 0.f, aA1 = 0.f, aA2 = 0.f, aA3 = 0.f;
    float aA4 = 0.f, aA5 = 0.f, aA6 = 0.f, aA7 = 0.f;
    float aB0 = 0.f, aB1 = 0.f, aB2 = 0.f, aB3 = 0.f;
    float aB4 = 0.f, aB5 = 0.f, aB6 = 0.f, aB7 = 0.f;

    int p = s + grp;
    int2 e0 = (p     < end) ? __ldcs(&g_epack[p])     : make_int2(0, 0);
    int2 e1 = (p + 4 < end) ? __ldcs(&g_epack[p + 4]) : make_int2(0, 0);

#pragma unroll 1
    while (p < end) {
        int2 f0 = (p + 8  < end) ? __ldcs(&g_epack[p + 8])  : make_int2(0, 0);
        int2 f1 = (p + 12 < end) ? __ldcs(&g_epack[p + 12]) : make_int2(0, 0);

        uint4 q0 = lg4[(size_t)e0.x * 8 + j];
        uint4 q1 = lg4[(size_t)e1.x * 8 + j];
        float v0 = __int_as_float(e0.y);
        float v1 = __int_as_float(e1.y);

        float2 g0 = __half22float2(*(const __half2*)&q0.x);
        float2 g1 = __half22float2(*(const __half2*)&q0.y);
        float2 g2 = __half22float2(*(const __half2*)&q0.z);
        float2 g3 = __half22float2(*(const __half2*)&q0.w);
        aA0 = fmaf(v0, g0.x, aA0); aA1 = fmaf(v0, g0.y, aA1);
        aA2 = fmaf(v0, g1.x, aA2); aA3 = fmaf(v0, g1.y, aA3);
        aA4 = fmaf(v0, g2.x, aA4); aA5 = fmaf(v0, g2.y, aA5);
        aA6 = fmaf(v0, g3.x, aA6); aA7 = fmaf(v0, g3.y, aA7);

        float2 h0 = __half22float2(*(const __half2*)&q1.x);
        float2 h1 = __half22float2(*(const __half2*)&q1.y);
        float2 h2 = __half22float2(*(const __half2*)&q1.z);
        float2 h3 = __half22float2(*(const __half2*)&q1.w);
        aB0 = fmaf(v1, h0.x, aB0); aB1 = fmaf(v1, h0.y, aB1);
        aB2 = fmaf(v1, h1.x, aB2); aB3 = fmaf(v1, h1.y, aB3);
        aB4 = fmaf(v1, h2.x, aB4); aB5 = fmaf(v1, h2.y, aB5);
        aB6 = fmaf(v1, h3.x, aB6); aB7 = fmaf(v1, h3.y, aB7);

        e0 = f0; e1 = f1; p += 8;
    }

    float a0 = aA0 + aB0, a1 = aA1 + aB1, a2 = aA2 + aB2, a3 = aA3 + aB3;
    float a4 = aA4 + aB4, a5 = aA5 + aB5, a6 = aA6 + aB6, a7 = aA7 + aB7;

#pragma unroll
    for (int d = 8; d <= 16; d <<= 1) {
        a0 += __shfl_xor_sync(0xffffffffu, a0, d);
        a1 += __shfl_xor_sync(0xffffffffu, a1, d);
        a2 += __shfl_xor_sync(0xffffffffu, a2, d);
        a3 += __shfl_xor_sync(0xffffffffu, a3, d);
        a4 += __shfl_xor_sync(0xffffffffu, a4, d);
        a5 += __shfl_xor_sync(0xffffffffu, a5, d);
        a6 += __shfl_xor_sync(0xffffffffu, a6, d);
        a7 += __shfl_xor_sync(0xffffffffu, a7, d);
    }

    if (grp == 0) {
        float4 o0; o0.x = a0; o0.y = a1; o0.z = a2; o0.w = a3;
        float4 o1; o1.x = a4; o1.y = a5; o1.z = a6; o1.w = a7;
        __stcs((float4*)(out + (size_t)n * NCLS + j * 8), o0);
        __stcs((float4*)(out + (size_t)n * NCLS + j * 8 + 4), o1);
    }
}

// ---------------------------------------------------------------------------
// Launch: fork the CSR-build chain onto a side stream so it overlaps the MLP.
// ---------------------------------------------------------------------------
extern "C" void kernel_launch(void* const* d_in, const int* in_sizes, int n_in,
                              void* d_out, int out_size)
{
    const float* X    = (const float*)d_in[0];
    const int*   erow = (const int*)  d_in[1];
    const int*   ecol = (const int*)  d_in[2];
    const float* ev   = (const float*)d_in[3];
    const float* W1   = (const float*)d_in[4];
    const float* b1   = (const float*)d_in[5];
    const float* W2   = (const float*)d_in[6];
    const float* b2   = (const float*)d_in[7];
    float* out = (float*)d_out;
    const int E = in_sizes[1];

    static bool attr_set = false;
    if (!attr_set) {
        cudaFuncSetAttribute(mlp_mma, cudaFuncAttributeMaxDynamicSharedMemorySize,
                             SMEM_WORDS * 4);
        attr_set = true;
    }

    cudaStream_t s2;
    cudaEvent_t evFork, evJoin;
    cudaStreamCreateWithFlags(&s2, cudaStreamNonBlocking);
    cudaEventCreateWithFlags(&evFork, cudaEventDisableTiming);
    cudaEventCreateWithFlags(&evJoin, cudaEventDisableTiming);

    cudaEventRecord(evFork, 0);
    cudaStreamWaitEvent(s2, evFork, 0);

    // Branch A (s2): CSR build chain.
    void* cnt_ptr = nullptr;
    cudaGetSymbolAddress(&cnt_ptr, g_cnt);
    cudaMemsetAsync(cnt_ptr, 0, N_NODES * sizeof(int), s2);
    const int eb4 = (E / 4 + 255) / 256;
    hist_k <<<eb4, 256, 0, s2>>>(erow, E);
    scan1_k<<<SCAN_NB, 256, 0, s2>>>(N_NODES);
    scan2_k<<<1, 128, 0, s2>>>(SCAN_NB);
    scan3_k<<<(N_NODES + 255) / 256, 256, 0, s2>>>(N_NODES);
    build_k<<<eb4, 256, 0, s2>>>(erow, ecol, ev, E);
    cudaEventRecord(evJoin, s2);

    // Branch B (origin stream): W1 convert then MLP.
    w1conv_k<<<64, 256>>>(W1);
    mlp_mma<<<(N_NODES + BM - 1) / BM, 256, SMEM_WORDS * 4>>>(X, b1, W2, b2);

    // Join, then reduce.
    cudaStreamWaitEvent(0, evJoin, 0);
    reduce_k<<<(N_NODES + 7) / 8, 256>>>(out);
}